// round 3
// baseline (speedup 1.0000x reference)
#include <cuda_runtime.h>
#include <math.h>

#define KCODES 512
#define DIM 64
#define NROWS 262144
#define TPB 256
#define NBLOCKS (NROWS / TPB)   // 1024
#define CHUNK 128               // codes per smem tile

// Scratch (no allocations allowed)
__device__ float  g_sw[KCODES];
__device__ int    g_counts[KCODES];
__device__ double g_partial[NBLOCKS];

// ---------------------------------------------------------------------------
// Kernel 1: per-code squared norms + zero histogram
// ---------------------------------------------------------------------------
__global__ void vq_prep(const float* __restrict__ W) {
    int k = threadIdx.x;
    if (k < KCODES) {
        const float* w = W + k * DIM;
        float s = 0.0f;
        #pragma unroll
        for (int d = 0; d < DIM; ++d) s += w[d] * w[d];
        g_sw[k] = s;
        g_counts[k] = 0;
    }
}

// ---------------------------------------------------------------------------
// Kernel 2: main — distances, argmin, quantized_st, loss partials, histogram
// Output layout (float32):
//   out[0]                      = loss
//   out[1 .. 1+N*64)            = quantized_st (row-major)   [4B-aligned only!]
//   out[1+N*64]                 = norm_perplexity
//   out[2+N*64 .. 2+N*64+N)     = encoding_indices (as float)
// ---------------------------------------------------------------------------
__global__ __launch_bounds__(TPB) void vq_main(const float* __restrict__ X,
                                               const float* __restrict__ W,
                                               float* __restrict__ out) {
    __shared__ float  s_tile[CHUNK * DIM];   // 32 KB
    __shared__ float  s_sw[KCODES];          // 2 KB
    __shared__ double s_red[TPB];            // 2 KB

    const int tid = threadIdx.x;
    const int row = blockIdx.x * TPB + tid;

    // stage code norms once
    for (int i = tid; i < KCODES; i += TPB) s_sw[i] = g_sw[i];

    // load this thread's row into registers (inputs are 16B aligned)
    float4 x[16];
    const float4* xp = (const float4*)(X + (size_t)row * DIM);
    #pragma unroll
    for (int g = 0; g < 16; ++g) x[g] = xp[g];

    // sx = sum(x^2)
    float sx = 0.0f;
    #pragma unroll
    for (int g = 0; g < 16; ++g) {
        sx += x[g].x * x[g].x;
        sx += x[g].y * x[g].y;
        sx += x[g].z * x[g].z;
        sx += x[g].w * x[g].w;
    }

    float best = INFINITY;
    int bestIdx = 0;

    for (int c = 0; c < KCODES / CHUNK; ++c) {
        __syncthreads();
        // cooperative, coalesced load of 128 codes (contiguous in W)
        {
            const float4* wp = (const float4*)(W + (size_t)c * CHUNK * DIM);
            float4* tp = (float4*)s_tile;
            for (int i = tid; i < CHUNK * (DIM / 4); i += TPB) tp[i] = wp[i];
        }
        __syncthreads();

        #pragma unroll 2
        for (int kk = 0; kk < CHUNK; ++kk) {
            const float4* wrow = (const float4*)(s_tile + kk * DIM);
            float dot = 0.0f;
            #pragma unroll
            for (int g = 0; g < 16; ++g) {
                float4 w4 = wrow[g];   // broadcast LDS.128 (all lanes same addr)
                dot += x[g].x * w4.x;
                dot += x[g].y * w4.y;
                dot += x[g].z * w4.z;
                dot += x[g].w * w4.w;
            }
            const int k = c * CHUNK + kk;
            float t = sx + s_sw[k];          // fl(sx + sw_k)
            float dist = t - 2.0f * dot;     // fl(t - 2*dot)
            if (dist < best) { best = dist; bestIdx = k; }  // first-min tie-break
        }
    }

    // gather chosen code, compute straight-through output + loss contribution.
    // quantized_st region starts at element offset 1 -> only 4B-aligned:
    // MUST use scalar 32-bit stores (float4 stores trap on misalignment).
    const float4* qp = (const float4*)(W + (size_t)bestIdx * DIM);
    float* op = out + 1 + (size_t)row * DIM;
    double lsum = 0.0;
    #pragma unroll
    for (int g = 0; g < 16; ++g) {
        float4 q4 = qp[g];
        float e;
        e = q4.x - x[g].x; op[4*g + 0] = x[g].x + e; lsum += (double)(e * e);
        e = q4.y - x[g].y; op[4*g + 1] = x[g].y + e; lsum += (double)(e * e);
        e = q4.z - x[g].z; op[4*g + 2] = x[g].z + e; lsum += (double)(e * e);
        e = q4.w - x[g].w; op[4*g + 3] = x[g].w + e; lsum += (double)(e * e);
    }

    // index output (as float)
    out[2 + (size_t)NROWS * DIM + row] = (float)bestIdx;

    // histogram
    atomicAdd(&g_counts[bestIdx], 1);

    // deterministic block tree reduction of loss partials (double)
    s_red[tid] = lsum;
    __syncthreads();
    for (int s = TPB / 2; s > 0; s >>= 1) {
        if (tid < s) s_red[tid] += s_red[tid + s];
        __syncthreads();
    }
    if (tid == 0) g_partial[blockIdx.x] = s_red[0];
}

// ---------------------------------------------------------------------------
// Kernel 3: finalize — loss + perplexity scalars
// ---------------------------------------------------------------------------
__global__ void vq_finalize(float* __restrict__ out) {
    __shared__ double sd[512];
    __shared__ float  sf[512];
    const int t = threadIdx.x;  // 512 threads

    double v = 0.0;
    for (int i = t; i < NBLOCKS; i += 512) v += g_partial[i];
    sd[t] = v;

    float c = (float)g_counts[t] / (float)NROWS;
    sf[t] = c * logf(c + 1e-10f);
    __syncthreads();

    for (int s = 256; s > 0; s >>= 1) {
        if (t < s) { sd[t] += sd[t + s]; sf[t] += sf[t + s]; }
        __syncthreads();
    }

    if (t == 0) {
        float m = (float)(sd[0] / ((double)NROWS * (double)DIM));
        float loss = m + 0.25f * m;     // q_latent + commitment * e_latent (equal means)
        out[0] = loss;
        float perp = expf(-sf[0]);
        out[1 + (size_t)NROWS * DIM] = perp / (float)KCODES;
    }
}

// ---------------------------------------------------------------------------
extern "C" void kernel_launch(void* const* d_in, const int* in_sizes, int n_in,
                              void* d_out, int out_size) {
    const float* X = (const float*)d_in[0];   // inputs  [N, 64]
    const float* W = (const float*)d_in[1];   // emb_weight [512, 64]
    float* out = (float*)d_out;

    int rows = in_sizes[0] / DIM;             // 262144
    int blocks = rows / TPB;                  // 1024

    vq_prep<<<1, KCODES>>>(W);
    vq_main<<<blocks, TPB>>>(X, W, out);
    vq_finalize<<<1, KCODES>>>(out);
}

// round 4
// speedup vs baseline: 1.2572x; 1.2572x over previous
#include <cuda_runtime.h>
#include <math.h>

#define KCODES 512
#define DIM 64
#define NROWS 262144
#define TPB 256
#define NBLOCKS (NROWS / TPB)   // 1024
#define CHUNK 128               // codes per smem tile
#define NPAIRS (CHUNK / 2)      // 64 code-pairs per tile

// Scratch (no allocations allowed)
__device__ float  g_sw[KCODES];
__device__ int    g_counts[KCODES];
__device__ double g_partial[NBLOCKS];

// packed fp32x2 helpers
__device__ __forceinline__ unsigned long long pack2(float lo, float hi) {
    unsigned long long r;
    asm("mov.b64 %0, {%1, %2};" : "=l"(r) : "f"(lo), "f"(hi));
    return r;
}
__device__ __forceinline__ void unpack2(unsigned long long v, float& lo, float& hi) {
    asm("mov.b64 {%0, %1}, %2;" : "=f"(lo), "=f"(hi) : "l"(v));
}
__device__ __forceinline__ unsigned long long fma2(unsigned long long a,
                                                   unsigned long long b,
                                                   unsigned long long c) {
    unsigned long long d;
    asm("fma.rn.f32x2 %0, %1, %2, %3;" : "=l"(d) : "l"(a), "l"(b), "l"(c));
    return d;
}
__device__ __forceinline__ unsigned long long add2(unsigned long long a,
                                                   unsigned long long b) {
    unsigned long long d;
    asm("add.rn.f32x2 %0, %1, %2;" : "=l"(d) : "l"(a), "l"(b));
    return d;
}

// ---------------------------------------------------------------------------
// Kernel 1: per-code squared norms + zero histogram (vectorized, multi-block)
// ---------------------------------------------------------------------------
__global__ void vq_prep(const float* __restrict__ W) {
    int k = blockIdx.x * 64 + threadIdx.x;   // grid 8 x 64
    const float4* w = (const float4*)(W + (size_t)k * DIM);
    float s = 0.0f;
    #pragma unroll
    for (int g = 0; g < 16; ++g) {
        float4 v = w[g];
        s += v.x * v.x; s += v.y * v.y; s += v.z * v.z; s += v.w * v.w;
    }
    g_sw[k] = s;
    g_counts[k] = 0;
}

// ---------------------------------------------------------------------------
// Kernel 2: main — packed-fp32x2 scoring, argmin, q_st, loss, histogram
// Output layout (float32):
//   out[0] = loss | out[1..1+N*64) = quantized_st | out[1+N*64] = perp
//   out[2+N*64 .. 2+N*64+N) = indices (float)
// ---------------------------------------------------------------------------
__global__ __launch_bounds__(TPB) void vq_main(const float* __restrict__ X,
                                               const float* __restrict__ W,
                                               float* __restrict__ out) {
    // pair-interleaved tile: s_pair[p*DIM + d] = {W[2p][d], W[2p+1][d]}
    __shared__ float2 s_pair[NPAIRS * DIM];  // 32 KB
    __shared__ float  s_sw[KCODES];          // 2 KB
    __shared__ double s_red[TPB];            // 2 KB

    const int tid = threadIdx.x;
    const int row = blockIdx.x * TPB + tid;

    for (int i = tid; i < KCODES; i += TPB) s_sw[i] = g_sw[i];

    // load row, compute sx, and pack x into {x[d], x[d]} (held across whole loop)
    unsigned long long xx[DIM];
    float sx = 0.0f;
    {
        const float4* xp = (const float4*)(X + (size_t)row * DIM);
        #pragma unroll
        for (int g = 0; g < 16; ++g) {
            float4 v = xp[g];
            sx += v.x * v.x; sx += v.y * v.y; sx += v.z * v.z; sx += v.w * v.w;
            xx[4*g + 0] = pack2(v.x, v.x);
            xx[4*g + 1] = pack2(v.y, v.y);
            xx[4*g + 2] = pack2(v.z, v.z);
            xx[4*g + 3] = pack2(v.w, v.w);
        }
    }

    float best = INFINITY;
    int bestIdx = 0;

    for (int c = 0; c < KCODES / CHUNK; ++c) {
        __syncthreads();
        // cooperative interleave: pair p, dim d  <-  codes 2p, 2p+1
        {
            const float* wb = W + (size_t)c * CHUNK * DIM;
            for (int i = tid; i < NPAIRS * DIM; i += TPB) {
                int p = i >> 6;          // /DIM
                int d = i & 63;
                s_pair[i] = make_float2(wb[(2 * p) * DIM + d],
                                        wb[(2 * p + 1) * DIM + d]);
            }
        }
        __syncthreads();

        for (int p = 0; p < NPAIRS; ++p) {
            const ulonglong2* wp = (const ulonglong2*)(s_pair + p * DIM);
            unsigned long long a0 = 0, a1 = 0, a2 = 0, a3 = 0;
            #pragma unroll
            for (int g = 0; g < 16; ++g) {          // 4 dims per iter
                ulonglong2 w01 = wp[2 * g];          // d = 4g, 4g+1 (LDS.128 bcast)
                ulonglong2 w23 = wp[2 * g + 1];      // d = 4g+2, 4g+3
                a0 = fma2(xx[4*g + 0], w01.x, a0);
                a1 = fma2(xx[4*g + 1], w01.y, a1);
                a2 = fma2(xx[4*g + 2], w23.x, a2);
                a3 = fma2(xx[4*g + 3], w23.y, a3);
            }
            unsigned long long dot2 = add2(add2(a0, a1), add2(a2, a3));
            float d0, d1;
            unpack2(dot2, d0, d1);
            const int k0 = c * CHUNK + 2 * p;
            float t0 = sx + s_sw[k0];
            float t1 = sx + s_sw[k0 + 1];
            float dist0 = t0 - 2.0f * d0;
            float dist1 = t1 - 2.0f * d1;
            if (dist0 < best) { best = dist0; bestIdx = k0; }      // ascending k,
            if (dist1 < best) { best = dist1; bestIdx = k0 + 1; }  // strict <
        }
    }

    // gather chosen code, straight-through output + loss contribution.
    // quantized_st region is only 4B-aligned -> scalar stores.
    const float4* qp = (const float4*)(W + (size_t)bestIdx * DIM);
    float* op = out + 1 + (size_t)row * DIM;
    double lsum = 0.0;
    #pragma unroll
    for (int g = 0; g < 16; ++g) {
        float4 q4 = qp[g];
        float xv, dummy, e;
        unpack2(xx[4*g + 0], xv, dummy);
        e = q4.x - xv; op[4*g + 0] = xv + e; lsum += (double)(e * e);
        unpack2(xx[4*g + 1], xv, dummy);
        e = q4.y - xv; op[4*g + 1] = xv + e; lsum += (double)(e * e);
        unpack2(xx[4*g + 2], xv, dummy);
        e = q4.z - xv; op[4*g + 2] = xv + e; lsum += (double)(e * e);
        unpack2(xx[4*g + 3], xv, dummy);
        e = q4.w - xv; op[4*g + 3] = xv + e; lsum += (double)(e * e);
    }

    out[2 + (size_t)NROWS * DIM + row] = (float)bestIdx;
    atomicAdd(&g_counts[bestIdx], 1);

    s_red[tid] = lsum;
    __syncthreads();
    for (int s = TPB / 2; s > 0; s >>= 1) {
        if (tid < s) s_red[tid] += s_red[tid + s];
        __syncthreads();
    }
    if (tid == 0) g_partial[blockIdx.x] = s_red[0];
}

// ---------------------------------------------------------------------------
// Kernel 3: finalize — loss + perplexity scalars
// ---------------------------------------------------------------------------
__global__ void vq_finalize(float* __restrict__ out) {
    __shared__ double sd[512];
    __shared__ float  sf[512];
    const int t = threadIdx.x;  // 512 threads

    double v = 0.0;
    for (int i = t; i < NBLOCKS; i += 512) v += g_partial[i];
    sd[t] = v;

    float c = (float)g_counts[t] / (float)NROWS;
    sf[t] = c * logf(c + 1e-10f);
    __syncthreads();

    for (int s = 256; s > 0; s >>= 1) {
        if (t < s) { sd[t] += sd[t + s]; sf[t] += sf[t + s]; }
        __syncthreads();
    }

    if (t == 0) {
        float m = (float)(sd[0] / ((double)NROWS * (double)DIM));
        out[0] = m + 0.25f * m;
        out[1 + (size_t)NROWS * DIM] = expf(-sf[0]) / (float)KCODES;
    }
}

// ---------------------------------------------------------------------------
extern "C" void kernel_launch(void* const* d_in, const int* in_sizes, int n_in,
                              void* d_out, int out_size) {
    const float* X = (const float*)d_in[0];   // inputs  [N, 64]
    const float* W = (const float*)d_in[1];   // emb_weight [512, 64]
    float* out = (float*)d_out;

    int rows = in_sizes[0] / DIM;             // 262144
    int blocks = rows / TPB;                  // 1024

    vq_prep<<<KCODES / 64, 64>>>(W);
    vq_main<<<blocks, TPB>>>(X, W, out);
    vq_finalize<<<1, KCODES>>>(out);
}